// round 17
// baseline (speedup 1.0000x reference)
#include <cuda_runtime.h>
#include <cuda_bf16.h>
#include <cstdint>

// TriLinear: out[b,q,k] = (Q.w1)[b,q] + (K.w2)[b,k] + sum_d Q[b,q,d]*w3[d]*K[b,k,d]
// B=32, L=1024, D=768.
//
// R16 post-mortem: three scheduling attacks all pinned at tensor~48% with
// tensor-busy ~170us -> the tf32 HMMA floor is the wall. This round converts
// the GEMM to a 3-term bf16 split (a=ah+al, b=bh+bl; ab ~ ah.bh+ah.bl+al.bh)
// on m16n8k16 (bf16 = 2x tf32 rate) -> 0.75x tensor-busy floor, better
// LDSM:MMA mix, and ~2e-5 precision (better than tf32's 1.7e-4).
//
//  1) prepass: split Q and (w3 (*) K) into bf16 hi/lo planes, layout
//     [row][k16-chunk][hi16|lo16] (64B per chunk); qlog/klog in fp32.
//  2) GEMM: 128x128 block, 4 warps of 64x64, 2 CTAs/SM, cp.async 5-stage,
//     ldmatrix.x4 fragments, 96 bf16 MMAs per warp per k16 chunk.

#define L_DIM 1024
#define D_DIM 768
#define NROWS (32 * L_DIM)
#define NCH   (D_DIM / 16)     // 48 k16 chunks
#define ROWB  (NCH * 64)       // 3072 bytes per row (48 chunks x 64B)

// ---- device scratch (static __device__ arrays: no allocs) ----
__device__ __nv_bfloat16 g_A[(size_t)NROWS * NCH * 32];   // 96 MB: Q hi/lo
__device__ __nv_bfloat16 g_B[(size_t)NROWS * NCH * 32];   // 96 MB: w3*K hi/lo
__device__ float g_qlog[NROWS];
__device__ float g_klog[NROWS];

// ============================ pre-pass ============================
// One warp per row r: split Q row and (w3*K) row into bf16 hi/lo planes,
// logits in fp32.
__global__ __launch_bounds__(256, 8)
void prepass_kernel(const float* __restrict__ Q,
                    const float* __restrict__ K,
                    const float* __restrict__ w1,
                    const float* __restrict__ w2,
                    const float* __restrict__ w3)
{
    const int wid  = threadIdx.x >> 5;
    const int lane = threadIdx.x & 31;
    const int row  = blockIdx.x * 8 + wid;

    const float4* q4  = (const float4*)(Q + (size_t)row * D_DIM);
    const float4* k4  = (const float4*)(K + (size_t)row * D_DIM);
    const float4* w14 = (const float4*)w1;
    const float4* w24 = (const float4*)w2;
    const float4* w34 = (const float4*)w3;
    __nv_bfloat16* arow = g_A + (size_t)row * NCH * 32;
    __nv_bfloat16* brow = g_B + (size_t)row * NCH * 32;

    float qp = 0.f, kp = 0.f;
    #pragma unroll
    for (int j = 0; j < 6; j++) {
        const int idx = j * 32 + lane;              // float4 index 0..191
        float4 qv = q4[idx], kv = k4[idx];
        float4 v1 = w14[idx], v2 = w24[idx], v3 = w34[idx];
        qp += qv.x*v1.x + qv.y*v1.y + qv.z*v1.z + qv.w*v1.w;
        kp += kv.x*v2.x + kv.y*v2.y + kv.z*v2.z + kv.w*v2.w;

        float av[4] = {qv.x, qv.y, qv.z, qv.w};
        float bv[4] = {kv.x * v3.x, kv.y * v3.y, kv.z * v3.z, kv.w * v3.w};
        __nv_bfloat16 ah[4], al[4], bh[4], bl[4];
        #pragma unroll
        for (int e = 0; e < 4; e++) {
            ah[e] = __float2bfloat16_rn(av[e]);
            al[e] = __float2bfloat16_rn(av[e] - __bfloat162float(ah[e]));
            bh[e] = __float2bfloat16_rn(bv[e]);
            bl[e] = __float2bfloat16_rn(bv[e] - __bfloat162float(bh[e]));
        }
        // chunk-interleaved layout: [chunk][hi:16 bf16 | lo:16 bf16]
        const int chunk = idx >> 2;                 // k16 chunk 0..47
        const int pos4  = (idx & 3) * 4;            // bf16 offset in hi16
        *(uint2*)(arow + chunk * 32 + pos4)      = *(uint2*)ah;
        *(uint2*)(arow + chunk * 32 + 16 + pos4) = *(uint2*)al;
        *(uint2*)(brow + chunk * 32 + pos4)      = *(uint2*)bh;
        *(uint2*)(brow + chunk * 32 + 16 + pos4) = *(uint2*)bl;
    }
    #pragma unroll
    for (int off = 16; off; off >>= 1) {
        qp += __shfl_xor_sync(0xffffffffu, qp, off);
        kp += __shfl_xor_sync(0xffffffffu, kp, off);
    }
    if (lane == 0) {
        g_qlog[row] = qp;
        g_klog[row] = kp;
    }
}

// ============================ GEMM ============================
#define BM    128
#define BN    128
#define NKT   NCH              // 48 k16 iterations
#define SKA   20               // row stride in 4B units (80B): rows hit all 32
                               // banks under LDSM -> conflict-free
#define THREADS 128
#define NSTAGE  5

#define SM_QLOG   0                        // 128 floats
#define SM_KLOG   512                      // 128 floats
#define SM_TILES  1024                     // 16B-aligned
#define A_STAGE_B (BM * SKA * 4)           // 10240 (128 rows x 80B)
#define B_STAGE_B (BN * SKA * 4)           // 10240
#define STAGE_B   (A_STAGE_B + B_STAGE_B)  // 20480
#define SM_TOTAL  (SM_TILES + NSTAGE * STAGE_B)   // 103424 (x2 CTAs = 207KB/SM)

__device__ __forceinline__ void mma_bf16(float* d, const uint32_t* a, const uint32_t* b) {
    asm volatile(
        "mma.sync.aligned.m16n8k16.row.col.f32.bf16.bf16.f32 "
        "{%0,%1,%2,%3}, {%4,%5,%6,%7}, {%8,%9}, {%0,%1,%2,%3};\n"
        : "+f"(d[0]), "+f"(d[1]), "+f"(d[2]), "+f"(d[3])
        : "r"(a[0]), "r"(a[1]), "r"(a[2]), "r"(a[3]),
          "r"(b[0]), "r"(b[1]));
}

__device__ __forceinline__ void ldsm4(uint32_t* r, uint32_t a) {
    asm volatile("ldmatrix.sync.aligned.m8n8.x4.shared.b16 {%0,%1,%2,%3}, [%4];"
                 : "=r"(r[0]), "=r"(r[1]), "=r"(r[2]), "=r"(r[3]) : "r"(a));
}

__device__ __forceinline__ uint32_t smem_u32(const void* p) {
    uint32_t a;
    asm("{ .reg .u64 t; cvta.to.shared.u64 t, %1; cvt.u32.u64 %0, t; }"
        : "=r"(a) : "l"(p));
    return a;
}

__device__ __forceinline__ void cpa16(uint32_t dst, const void* src) {
    asm volatile("cp.async.cg.shared.global [%0], [%1], 16;"
                 :: "r"(dst), "l"(src) : "memory");
}

__device__ __forceinline__ void cpa_commit() {
    asm volatile("cp.async.commit_group;" ::: "memory");
}

__device__ __forceinline__ void cpa_wait3() {
    asm volatile("cp.async.wait_group 3;" ::: "memory");
}

__global__ __launch_bounds__(THREADS, 2)
void trilinear_gemm(float* __restrict__ out)
{
    extern __shared__ char smc[];
    const uint32_t sb = smem_u32(smc);

    const int t    = threadIdx.x;
    const int lane = t & 31;
    const int wid  = t >> 5;          // 0..3
    const int wm   = wid >> 1;        // 0..1  (64-row slice)
    const int wn   = wid & 1;         // 0..1  (64-col slice)
    const int gr   = lane >> 2;       // 0..7
    const int gc   = lane & 3;        // 0..3

    const int bn = blockIdx.x, bm = blockIdx.y, bb = blockIdx.z;
    const char* Agr = (const char*)g_A + (size_t)(bb * L_DIM + bm * BM) * ROWB;
    const char* Bgr = (const char*)g_B + (size_t)(bb * L_DIM + bn * BN) * ROWB;

    // producer mapping: 4 consecutive threads cover one 64B row-chunk
    const int prow = t >> 2;          // 0..31
    const int pkq  = t & 3;           // which 16B of the 64B chunk

    // ---- stage qlog/klog into smem (ordinary LDG; visible after 1st sync) ----
    {
        float* ql = (float*)(smc + SM_QLOG);
        float* kl = (float*)(smc + SM_KLOG);
        ql[t] = g_qlog[bb * L_DIM + bm * BM + t];
        kl[t] = g_klog[bb * L_DIM + bn * BN + t];
    }

    auto issue_stage = [&](int c) {
        const int s = c % NSTAGE;
        const uint32_t abase = sb + SM_TILES + s * STAGE_B;
        const uint32_t bbase = abase + A_STAGE_B;
        #pragma unroll
        for (int i = 0; i < 4; i++) {
            const int r = prow + 32 * i;
            cpa16(abase + (uint32_t)(r * SKA + pkq * 4) * 4,
                  Agr + (size_t)r * ROWB + c * 64 + pkq * 16);
            cpa16(bbase + (uint32_t)(r * SKA + pkq * 4) * 4,
                  Bgr + (size_t)r * ROWB + c * 64 + pkq * 16);
        }
    };

    float acc[4][8][4];
    #pragma unroll
    for (int i = 0; i < 4; i++)
        #pragma unroll
        for (int j = 0; j < 8; j++)
            #pragma unroll
            for (int k2 = 0; k2 < 4; k2++)
                acc[i][j][k2] = 0.f;

    // ---- ldmatrix per-lane base offsets (within a stage) ----
    // Row layout: [hi: k0-7 (16B) | k8-15 (16B) | lo: k0-7 | k8-15], stride 80B.
    // A (x4): t0=(rows lo,+0) t1=(rows hi,+0) t2=(rows lo,+16B) t3=(hi,+16B)
    //   -> regs r0..r3 = a0..a3 of m16n8k16 A fragment.
    const int tA = lane >> 3, rA = lane & 7;
    const uint32_t aOffH = (uint32_t)((wm * 64 + (tA & 1) * 8 + rA) * SKA) * 4
                         + (uint32_t)(tA >> 1) * 16;
    // B (x4): t0=(n lo,+0) t1=(n lo,+16B) t2=(n hi,+0) t3=(n hi,+16B)
    //   -> r0,r1 = {b0,b1} of nf=2p ; r2,r3 = {b0,b1} of nf=2p+1
    const uint32_t bOffH = (uint32_t)((wn * 64 + (tA >> 1) * 8 + rA) * SKA) * 4
                         + (uint32_t)(tA & 1) * 16;

    // ---- prologue: fill 4 of 5 stages ----
    issue_stage(0); cpa_commit();
    issue_stage(1); cpa_commit();
    issue_stage(2); cpa_commit();
    issue_stage(3); cpa_commit();

    // Invariant: before the wait in iter c there are 4+c commits; wait_group 3
    // -> stage c complete. issue_stage(c+4) writes buffer (c+4)%5 == (c-1)%5,
    // whose reads completed before the __syncthreads at top of iter c.
    for (int c = 0; c < NKT; c++) {
        cpa_wait3();
        __syncthreads();

        if (c + 4 < NKT) issue_stage(c + 4);
        cpa_commit();

        const int s = c % NSTAGE;
        const uint32_t aBase = sb + SM_TILES + s * STAGE_B;
        const uint32_t bBase = aBase + A_STAGE_B;

        uint32_t ah[4][4], al[4][4], bh[4][4], bl[4][4];
        #pragma unroll
        for (int mf = 0; mf < 4; mf++) {
            const uint32_t ra = aBase + aOffH + (uint32_t)(mf * 16 * SKA) * 4;
            ldsm4(ah[mf], ra);
            ldsm4(al[mf], ra + 32);
        }
        #pragma unroll
        for (int p = 0; p < 4; p++) {
            const uint32_t rb = bBase + bOffH + (uint32_t)(p * 16 * SKA) * 4;
            ldsm4(bh[p], rb);
            ldsm4(bl[p], rb + 32);
        }

        // 3-term split: grouped so same-acc MMAs are 32 apart (no RAW stall)
        #pragma unroll
        for (int mf = 0; mf < 4; mf++)
            #pragma unroll
            for (int p = 0; p < 4; p++) {
                mma_bf16(acc[mf][2 * p    ], ah[mf], &bh[p][0]);
                mma_bf16(acc[mf][2 * p + 1], ah[mf], &bh[p][2]);
            }
        #pragma unroll
        for (int mf = 0; mf < 4; mf++)
            #pragma unroll
            for (int p = 0; p < 4; p++) {
                mma_bf16(acc[mf][2 * p    ], ah[mf], &bl[p][0]);
                mma_bf16(acc[mf][2 * p + 1], ah[mf], &bl[p][2]);
            }
        #pragma unroll
        for (int mf = 0; mf < 4; mf++)
            #pragma unroll
            for (int p = 0; p < 4; p++) {
                mma_bf16(acc[mf][2 * p    ], al[mf], &bh[p][0]);
                mma_bf16(acc[mf][2 * p + 1], al[mf], &bh[p][2]);
            }
    }
    __syncthreads();

    // ---- epilogue: out = dot + qlog[q] + klog[k] ----
    const float* qlog_s = (const float*)(smc + SM_QLOG);
    const float* klog_s = (const float*)(smc + SM_KLOG);
    float* Ob = out + ((size_t)bb * L_DIM + (size_t)bm * BM) * L_DIM + (size_t)bn * BN;
    #pragma unroll
    for (int mf = 0; mf < 4; mf++) {
        const int mo    = wm * 64 + mf * 16;
        const float ql0 = qlog_s[mo + gr];
        const float ql1 = qlog_s[mo + gr + 8];
        #pragma unroll
        for (int nf = 0; nf < 8; nf++) {
            const int no    = wn * 64 + nf * 8 + 2 * gc;
            const float kl0 = klog_s[no];
            const float kl1 = klog_s[no + 1];
            float2 v0, v1;
            v0.x = acc[mf][nf][0] + ql0 + kl0;
            v0.y = acc[mf][nf][1] + ql0 + kl1;
            v1.x = acc[mf][nf][2] + ql1 + kl0;
            v1.y = acc[mf][nf][3] + ql1 + kl1;
            *reinterpret_cast<float2*>(Ob + (size_t)(mo + gr    ) * L_DIM + no) = v0;
            *reinterpret_cast<float2*>(Ob + (size_t)(mo + gr + 8) * L_DIM + no) = v1;
        }
    }
}

extern "C" void kernel_launch(void* const* d_in, const int* in_sizes, int n_in,
                              void* d_out, int out_size)
{
    const float* Q  = (const float*)d_in[0];
    const float* K  = (const float*)d_in[1];
    const float* w1 = (const float*)d_in[2];
    const float* w2 = (const float*)d_in[3];
    const float* w3 = (const float*)d_in[4];

    cudaFuncSetAttribute(trilinear_gemm,
                         cudaFuncAttributeMaxDynamicSharedMemorySize, SM_TOTAL);

    prepass_kernel<<<NROWS / 8, 256>>>(Q, K, w1, w2, w3);

    dim3 grid(L_DIM / BN, L_DIM / BM, 32);   // (8, 8, 32)
    trilinear_gemm<<<grid, THREADS, SM_TOTAL>>>((float*)d_out);
}